// round 1
// baseline (speedup 1.0000x reference)
#include <cuda_runtime.h>
#include <cstdint>

#define D     512
#define NH    8
#define HD    64
#define WN    5
#define BATCH 4
#define SEQ   4096
#define MTOT  (BATCH * SEQ)

// Scratch: q, k, v each [MTOT, D] fp32 (static device allocation, ~100 MB)
__device__ float g_qkv[3ull * MTOT * D];

// ---------------------------------------------------------------------------
// Kernel 1: QKV projection GEMM. blockIdx.z selects {Wq,Wk,Wv}.
// Classic 128x128 block tile, 8x8 per thread, BK=8, 256 threads.
// ---------------------------------------------------------------------------
#define BM 128
#define BN 128
#define BK 8
#define TM 8
#define TN 8

__global__ __launch_bounds__(256) void qkv_gemm(
    const float* __restrict__ X,
    const float* __restrict__ Wq, const float* __restrict__ bq,
    const float* __restrict__ Wk, const float* __restrict__ bk,
    const float* __restrict__ Wv, const float* __restrict__ bv)
{
    const int z = blockIdx.z;
    const float* Wm   = (z == 0) ? Wq : (z == 1 ? Wk : Wv);
    const float* bias = (z == 0) ? bq : (z == 1 ? bk : bv);
    float* O = g_qkv + (size_t)z * MTOT * D;

    __shared__ float As[BK][BM];
    __shared__ float Bs[BK][BN + 4];   // +4 keeps rows 16B-aligned (132*4=528=33*16)

    const int tid = threadIdx.x;
    const int bm = blockIdx.y * BM;
    const int bn = blockIdx.x * BN;

    // A tile loads: 128 rows x 8 cols, one float4 per thread
    const int arow = tid >> 1;
    const int acol = (tid & 1) * 4;
    // B tile loads: 8 rows x 128 cols, one float4 per thread
    const int brow = tid >> 5;
    const int bcol = (tid & 31) * 4;

    const int tr = (tid >> 4) * TM;
    const int tc = (tid & 15) * TN;

    float acc[TM][TN];
#pragma unroll
    for (int i = 0; i < TM; i++)
#pragma unroll
        for (int j = 0; j < TN; j++) acc[i][j] = 0.f;

    const float* Ab = X + (size_t)bm * D;

    for (int k0 = 0; k0 < D; k0 += BK) {
        float4 a4 = *reinterpret_cast<const float4*>(Ab + (size_t)arow * D + k0 + acol);
        As[acol + 0][arow] = a4.x;
        As[acol + 1][arow] = a4.y;
        As[acol + 2][arow] = a4.z;
        As[acol + 3][arow] = a4.w;
        float4 b4 = *reinterpret_cast<const float4*>(Wm + (size_t)(k0 + brow) * D + bn + bcol);
        *reinterpret_cast<float4*>(&Bs[brow][bcol]) = b4;
        __syncthreads();

#pragma unroll
        for (int k = 0; k < BK; ++k) {
            float ra[TM], rb[TN];
#pragma unroll
            for (int i = 0; i < TM; i++) ra[i] = As[k][tr + i];
#pragma unroll
            for (int j = 0; j < TN; j++) rb[j] = Bs[k][tc + j];
#pragma unroll
            for (int i = 0; i < TM; i++)
#pragma unroll
                for (int j = 0; j < TN; j++)
                    acc[i][j] = fmaf(ra[i], rb[j], acc[i][j]);
        }
        __syncthreads();
    }

#pragma unroll
    for (int i = 0; i < TM; i++) {
        size_t row = (size_t)(bm + tr + i);
        float* orow = O + row * D + bn + tc;
#pragma unroll
        for (int j = 0; j < TN; j += 4) {
            float4 o;
            o.x = acc[i][j + 0] + bias[bn + tc + j + 0];
            o.y = acc[i][j + 1] + bias[bn + tc + j + 1];
            o.z = acc[i][j + 2] + bias[bn + tc + j + 2];
            o.w = acc[i][j + 3] + bias[bn + tc + j + 3];
            *reinterpret_cast<float4*>(orow + j) = o;
        }
    }
}

// ---------------------------------------------------------------------------
// Kernel 2: dilated windowed attention. One warp per (b, h, t).
// Window offsets: t + dil*(shift(h) + w - 2), out-of-range -> masked (zero k).
// ---------------------------------------------------------------------------
__global__ __launch_bounds__(256) void attn_kernel(
    const float* __restrict__ Er,
    const int*   __restrict__ layer_p,
    float* __restrict__ out,
    float* __restrict__ attn_out)
{
    const int gwarp = (int)((blockIdx.x * blockDim.x + threadIdx.x) >> 5);
    const int lane  = threadIdx.x & 31;
    if (gwarp >= BATCH * NH * SEQ) return;

    const int t = gwarp & (SEQ - 1);
    const int h = (gwarp >> 12) & (NH - 1);
    const int b = gwarp >> 15;

    const int dil = 1 << layer_p[0];
    const int shift_tab[8] = {0, 0, 0, 0, -2, -1, 1, 2};
    const int s = shift_tab[h];

    const float* Q  = g_qkv + ((size_t)(b * SEQ + t) * D + h * HD);
    const float* Kb = g_qkv + (size_t)MTOT * D;
    const float* Vb = g_qkv + 2ull * MTOT * D;

    const float2 q2 = reinterpret_cast<const float2*>(Q)[lane];
    const int d0 = h * HD + 2 * lane;

    int  tk[WN];
    bool valid[WN];
    float lg[WN];

#pragma unroll
    for (int w = 0; w < WN; w++) {
        const int tt = t + dil * (s + w - 2);
        const bool ok = (tt >= 0) && (tt < SEQ);
        tk[w] = tt;
        valid[w] = ok;
        float qk = 0.f;
        if (ok) {
            const float2 k2 = reinterpret_cast<const float2*>(
                Kb + ((size_t)(b * SEQ + tt) * D + h * HD))[lane];
            qk = q2.x * k2.x + q2.y * k2.y;
        }
        float er = q2.x * Er[(size_t)d0 * WN + w] + q2.y * Er[(size_t)(d0 + 1) * WN + w];
#pragma unroll
        for (int o = 16; o > 0; o >>= 1) {
            qk += __shfl_xor_sync(0xffffffffu, qk, o);
            er += __shfl_xor_sync(0xffffffffu, er, o);
        }
        lg[w] = ok ? (qk + er) * 0.125f : -1e30f;
    }

    float mx = lg[0];
#pragma unroll
    for (int w = 1; w < WN; w++) mx = fmaxf(mx, lg[w]);

    float p[WN];
    float sum = 0.f;
#pragma unroll
    for (int w = 0; w < WN; w++) {
        p[w] = valid[w] ? __expf(lg[w] - mx) : 0.f;
        sum += p[w];
    }
    const float inv = 1.f / sum;

    float ox = 0.f, oy = 0.f;
#pragma unroll
    for (int w = 0; w < WN; w++) {
        if (valid[w]) {
            const float a = p[w] * inv;
            const float2 v2 = reinterpret_cast<const float2*>(
                Vb + ((size_t)(b * SEQ + tk[w]) * D + h * HD))[lane];
            ox = fmaf(a, v2.x, ox);
            oy = fmaf(a, v2.y, oy);
        }
    }
    reinterpret_cast<float2*>(out + ((size_t)(b * SEQ + t) * D + h * HD))[lane] =
        make_float2(ox, oy);

    if (attn_out != nullptr && lane < WN) {
        float a = p[0];
        if (lane == 1) a = p[1];
        else if (lane == 2) a = p[2];
        else if (lane == 3) a = p[3];
        else if (lane == 4) a = p[4];
        attn_out[((size_t)((b * NH + h) * SEQ + t)) * WN + lane] = a * inv;
    }
}

// ---------------------------------------------------------------------------
extern "C" void kernel_launch(void* const* d_in, const int* in_sizes, int n_in,
                              void* d_out, int out_size)
{
    (void)in_sizes; (void)n_in;
    const float* X  = (const float*)d_in[0];
    const float* Wq = (const float*)d_in[1];
    const float* bq = (const float*)d_in[2];
    const float* Wk = (const float*)d_in[3];
    const float* bk = (const float*)d_in[4];
    const float* Wv = (const float*)d_in[5];
    const float* bv = (const float*)d_in[6];
    const float* Er = (const float*)d_in[7];
    const int* layer = (const int*)d_in[8];

    float* out = (float*)d_out;
    float* attn_out = nullptr;
    const long long OUTN = (long long)MTOT * D;                 // 8388608
    const long long ATTN = (long long)BATCH * NH * SEQ * WN;    // 655360
    if ((long long)out_size >= OUTN + ATTN) attn_out = out + OUTN;

    dim3 grid(D / BN, MTOT / BM, 3);
    qkv_gemm<<<grid, 256>>>(X, Wq, bq, Wk, bk, Wv, bv);

    const int warps = BATCH * NH * SEQ;
    const int blocks = (warps * 32 + 255) / 256;
    attn_kernel<<<blocks, 256>>>(Er, layer, out, attn_out);
}

// round 3
// speedup vs baseline: 2.1908x; 2.1908x over previous
#include <cuda_runtime.h>
#include <cuda_bf16.h>
#include <cstdint>

#define D     512
#define NH    8
#define HD    64
#define WN    5
#define BATCH 4
#define SEQ   4096
#define MTOT  (BATCH * SEQ)

// ---------------- scratch (static device allocations) ----------------
__device__ float         g_qkv[3ull * MTOT * D];          // q,k,v fp32
__device__ __nv_bfloat16 g_Xhi[(size_t)MTOT * D];
__device__ __nv_bfloat16 g_Xlo[(size_t)MTOT * D];
__device__ __nv_bfloat16 g_Whi[3ull * D * D];             // transposed: [n][k]
__device__ __nv_bfloat16 g_Wlo[3ull * D * D];

// ---------------- PTX helpers ----------------
__device__ __forceinline__ uint32_t smem_u32(const void* p) {
    uint32_t a;
    asm("{ .reg .u64 t; cvta.to.shared.u64 t, %1; cvt.u32.u64 %0, t; }" : "=r"(a) : "l"(p));
    return a;
}
__device__ __forceinline__ void cp16(uint32_t dst, const void* src) {
    asm volatile("cp.async.cg.shared.global [%0], [%1], 16;" :: "r"(dst), "l"(src));
}
#define CP_COMMIT() asm volatile("cp.async.commit_group;" ::: "memory")
#define CP_WAIT(n)  asm volatile("cp.async.wait_group %0;" :: "n"(n) : "memory")

#define LDSM4(r, addr) \
    asm volatile("ldmatrix.sync.aligned.m8n8.x4.shared.b16 {%0,%1,%2,%3}, [%4];" \
        : "=r"((r)[0]), "=r"((r)[1]), "=r"((r)[2]), "=r"((r)[3]) : "r"(addr))

#define MMA_BF16(c, a, b) \
    asm volatile("mma.sync.aligned.m16n8k16.row.col.f32.bf16.bf16.f32 " \
        "{%0,%1,%2,%3},{%4,%5,%6,%7},{%8,%9},{%0,%1,%2,%3};" \
        : "+f"((c)[0]), "+f"((c)[1]), "+f"((c)[2]), "+f"((c)[3]) \
        : "r"((a)[0]), "r"((a)[1]), "r"((a)[2]), "r"((a)[3]), "r"((b)[0]), "r"((b)[1]))

// ---------------- bf16 hi/lo split conversion ----------------
__device__ __forceinline__ void split_bf16(float x, unsigned short& h, unsigned short& l) {
    __nv_bfloat16 hb = __float2bfloat16(x);
    __nv_bfloat16 lb = __float2bfloat16(x - __bfloat162float(hb));
    h = __bfloat16_as_ushort(hb);
    l = __bfloat16_as_ushort(lb);
}

__global__ __launch_bounds__(256) void convert_x(const float* __restrict__ X) {
    size_t i = (size_t)blockIdx.x * 256 + threadIdx.x;   // float4 index
    float4 v = reinterpret_cast<const float4*>(X)[i];
    unsigned short h0, h1, h2, h3, l0, l1, l2, l3;
    split_bf16(v.x, h0, l0); split_bf16(v.y, h1, l1);
    split_bf16(v.z, h2, l2); split_bf16(v.w, h3, l3);
    uint2 hh = make_uint2((uint32_t)h0 | ((uint32_t)h1 << 16), (uint32_t)h2 | ((uint32_t)h3 << 16));
    uint2 ll = make_uint2((uint32_t)l0 | ((uint32_t)l1 << 16), (uint32_t)l2 | ((uint32_t)l3 << 16));
    reinterpret_cast<uint2*>(g_Xhi)[i] = hh;
    reinterpret_cast<uint2*>(g_Xlo)[i] = ll;
}

__global__ __launch_bounds__(256) void convert_w(const float* __restrict__ Wq,
                                                 const float* __restrict__ Wk,
                                                 const float* __restrict__ Wv) {
    int idx = blockIdx.x * 256 + threadIdx.x;   // < 3*512*512
    int z = idx >> 18;
    int r = idx & 262143;
    int k = r >> 9;
    int n = r & 511;
    const float* W = (z == 0) ? Wq : (z == 1 ? Wk : Wv);
    float x = W[(size_t)k * D + n];
    unsigned short h, l;
    split_bf16(x, h, l);
    size_t di = (size_t)z * D * D + (size_t)n * D + k;   // transposed [n][k]
    g_Whi[di] = __ushort_as_bfloat16(h);
    g_Wlo[di] = __ushort_as_bfloat16(l);
}

// ---------------- mma.sync GEMM: g_qkv[z] = X @ W[z] + b[z] ----------------
#define BM 128
#define BN 128
#define BK 32
#define NKIT (D / BK)            // 16
#define PADK 40                  // row stride in bf16 elements (80 B, 16B-aligned)
#define TILE_BYTES (128 * PADK * 2)          // 10240
#define SOFF_AHI 0
#define SOFF_ALO (1 * TILE_BYTES)
#define SOFF_BHI (2 * TILE_BYTES)
#define SOFF_BLO (3 * TILE_BYTES)
#define STAGE_BYTES (4 * TILE_BYTES)         // 40960
#define GEMM_SMEM (2 * STAGE_BYTES)          // 81920

__device__ __forceinline__ void load_stage(
    uint32_t sb, int stage, int m0, int n0, int kc,
    const __nv_bfloat16* __restrict__ Wh, const __nv_bfloat16* __restrict__ Wl, int tid)
{
    const uint32_t base = sb + stage * STAGE_BYTES;
#pragma unroll
    for (int p = 0; p < 2; ++p) {
        const int q = tid + p * 256;
        const int r = q >> 2, c = q & 3;
        const uint32_t doff = (uint32_t)(r * PADK + c * 8) * 2;
        const size_t asrc = (size_t)(m0 + r) * D + kc + c * 8;
        cp16(base + SOFF_AHI + doff, g_Xhi + asrc);
        cp16(base + SOFF_ALO + doff, g_Xlo + asrc);
        const size_t bsrc = (size_t)(n0 + r) * D + kc + c * 8;
        cp16(base + SOFF_BHI + doff, Wh + bsrc);
        cp16(base + SOFF_BLO + doff, Wl + bsrc);
    }
}

__global__ __launch_bounds__(256) void qkv_gemm_mma(
    const float* __restrict__ bq, const float* __restrict__ bk, const float* __restrict__ bv)
{
    extern __shared__ char smem[];
    const uint32_t sb = smem_u32(smem);

    const int tid = threadIdx.x;
    const int wid = tid >> 5;
    const int lane = tid & 31;
    const int warp_m = wid >> 2;      // 0..1
    const int warp_n = wid & 3;       // 0..3

    const int m0 = blockIdx.x * BM;
    const int n0 = blockIdx.y * BN;
    const int z = blockIdx.z;

    const __nv_bfloat16* Wh = g_Whi + (size_t)z * D * D;
    const __nv_bfloat16* Wl = g_Wlo + (size_t)z * D * D;
    float* O = g_qkv + (size_t)z * MTOT * D;
    const float* bias = (z == 0) ? bq : (z == 1 ? bk : bv);

    float acc[4][4][4];
#pragma unroll
    for (int i = 0; i < 4; i++)
#pragma unroll
        for (int j = 0; j < 4; j++)
#pragma unroll
            for (int e = 0; e < 4; e++) acc[i][j][e] = 0.f;

    load_stage(sb, 0, m0, n0, 0, Wh, Wl, tid);
    CP_COMMIT();

    for (int kt = 0; kt < NKIT; ++kt) {
        const int buf = kt & 1;
        if (kt + 1 < NKIT) {
            load_stage(sb, buf ^ 1, m0, n0, (kt + 1) * BK, Wh, Wl, tid);
            CP_COMMIT();
            CP_WAIT(1);
        } else {
            CP_WAIT(0);
        }
        __syncthreads();

        const uint32_t stg = sb + buf * STAGE_BYTES;
#pragma unroll
        for (int ks = 0; ks < 2; ++ks) {
            uint32_t ah[4][4], al[4][4], bh[4][2], bl[4][2];
            // A fragments (hi, lo)
#pragma unroll
            for (int i = 0; i < 4; ++i) {
                const int row = warp_m * 64 + i * 16 + (lane & 15);
                const int col = ks * 16 + ((lane >> 4) << 3);
                const uint32_t off = (uint32_t)(row * PADK + col) * 2;
                LDSM4(ah[i], stg + SOFF_AHI + off);
                LDSM4(al[i], stg + SOFF_ALO + off);
            }
            // B fragments (hi, lo): x4 covers two n8 frags
#pragma unroll
            for (int j2 = 0; j2 < 2; ++j2) {
                const int nr = warp_n * 32 + j2 * 16 + ((lane >> 4) << 3) + (lane & 7);
                const int kc2 = ks * 16 + (((lane >> 3) & 1) << 3);
                const uint32_t off = (uint32_t)(nr * PADK + kc2) * 2;
                uint32_t t[4];
                LDSM4(t, stg + SOFF_BHI + off);
                bh[2 * j2][0] = t[0]; bh[2 * j2][1] = t[1];
                bh[2 * j2 + 1][0] = t[2]; bh[2 * j2 + 1][1] = t[3];
                LDSM4(t, stg + SOFF_BLO + off);
                bl[2 * j2][0] = t[0]; bl[2 * j2][1] = t[1];
                bl[2 * j2 + 1][0] = t[2]; bl[2 * j2 + 1][1] = t[3];
            }
#pragma unroll
            for (int i = 0; i < 4; ++i)
#pragma unroll
                for (int j = 0; j < 4; ++j) {
                    MMA_BF16(acc[i][j], ah[i], bh[j]);   // hi*hi
                    MMA_BF16(acc[i][j], ah[i], bl[j]);   // hi*lo
                    MMA_BF16(acc[i][j], al[i], bh[j]);   // lo*hi
                }
        }
        __syncthreads();
    }

    // ---- epilogue: direct STG with bias ----
#pragma unroll
    for (int j = 0; j < 4; ++j) {
        const int ncol = n0 + warp_n * 32 + j * 8 + (lane & 3) * 2;
        const float2 bb = *reinterpret_cast<const float2*>(bias + ncol);
#pragma unroll
        for (int i = 0; i < 4; ++i) {
            const int row0 = m0 + warp_m * 64 + i * 16 + (lane >> 2);
            float2 v0 = make_float2(acc[i][j][0] + bb.x, acc[i][j][1] + bb.y);
            float2 v1 = make_float2(acc[i][j][2] + bb.x, acc[i][j][3] + bb.y);
            *reinterpret_cast<float2*>(O + (size_t)row0 * D + ncol) = v0;
            *reinterpret_cast<float2*>(O + (size_t)(row0 + 8) * D + ncol) = v1;
        }
    }
}

// ---------------- attention (unchanged) ----------------
__global__ __launch_bounds__(256) void attn_kernel(
    const float* __restrict__ Er,
    const int*   __restrict__ layer_p,
    float* __restrict__ out,
    float* __restrict__ attn_out)
{
    const int gwarp = (int)((blockIdx.x * blockDim.x + threadIdx.x) >> 5);
    const int lane  = threadIdx.x & 31;
    if (gwarp >= BATCH * NH * SEQ) return;

    const int t = gwarp & (SEQ - 1);
    const int h = (gwarp >> 12) & (NH - 1);
    const int b = gwarp >> 15;

    const int dil = 1 << layer_p[0];
    const int shift_tab[8] = {0, 0, 0, 0, -2, -1, 1, 2};
    const int s = shift_tab[h];

    const float* Q  = g_qkv + ((size_t)(b * SEQ + t) * D + h * HD);
    const float* Kb = g_qkv + (size_t)MTOT * D;
    const float* Vb = g_qkv + 2ull * MTOT * D;

    const float2 q2 = reinterpret_cast<const float2*>(Q)[lane];
    const int d0 = h * HD + 2 * lane;

    int  tk[WN];
    bool valid[WN];
    float lg[WN];

#pragma unroll
    for (int w = 0; w < WN; w++) {
        const int tt = t + dil * (s + w - 2);
        const bool ok = (tt >= 0) && (tt < SEQ);
        tk[w] = tt;
        valid[w] = ok;
        float qk = 0.f;
        if (ok) {
            const float2 k2 = reinterpret_cast<const float2*>(
                Kb + ((size_t)(b * SEQ + tt) * D + h * HD))[lane];
            qk = q2.x * k2.x + q2.y * k2.y;
        }
        float er = q2.x * Er[(size_t)d0 * WN + w] + q2.y * Er[(size_t)(d0 + 1) * WN + w];
#pragma unroll
        for (int o = 16; o > 0; o >>= 1) {
            qk += __shfl_xor_sync(0xffffffffu, qk, o);
            er += __shfl_xor_sync(0xffffffffu, er, o);
        }
        lg[w] = ok ? (qk + er) * 0.125f : -1e30f;
    }

    float mx = lg[0];
#pragma unroll
    for (int w = 1; w < WN; w++) mx = fmaxf(mx, lg[w]);

    float p[WN];
    float sum = 0.f;
#pragma unroll
    for (int w = 0; w < WN; w++) {
        p[w] = valid[w] ? __expf(lg[w] - mx) : 0.f;
        sum += p[w];
    }
    const float inv = 1.f / sum;

    float ox = 0.f, oy = 0.f;
#pragma unroll
    for (int w = 0; w < WN; w++) {
        if (valid[w]) {
            const float a = p[w] * inv;
            const float2 v2 = reinterpret_cast<const float2*>(
                Vb + ((size_t)(b * SEQ + tk[w]) * D + h * HD))[lane];
            ox = fmaf(a, v2.x, ox);
            oy = fmaf(a, v2.y, oy);
        }
    }
    reinterpret_cast<float2*>(out + ((size_t)(b * SEQ + t) * D + h * HD))[lane] =
        make_float2(ox, oy);

    if (attn_out != nullptr && lane < WN) {
        float a = p[0];
        if (lane == 1) a = p[1];
        else if (lane == 2) a = p[2];
        else if (lane == 3) a = p[3];
        else if (lane == 4) a = p[4];
        attn_out[((size_t)((b * NH + h) * SEQ + t)) * WN + lane] = a * inv;
    }
}

// ---------------------------------------------------------------------------
extern "C" void kernel_launch(void* const* d_in, const int* in_sizes, int n_in,
                              void* d_out, int out_size)
{
    (void)in_sizes; (void)n_in;
    const float* X  = (const float*)d_in[0];
    const float* Wq = (const float*)d_in[1];
    const float* bq = (const float*)d_in[2];
    const float* Wk = (const float*)d_in[3];
    const float* bk = (const float*)d_in[4];
    const float* Wv = (const float*)d_in[5];
    const float* bv = (const float*)d_in[6];
    const float* Er = (const float*)d_in[7];
    const int* layer = (const int*)d_in[8];

    float* out = (float*)d_out;
    float* attn_out = nullptr;
    const long long OUTN = (long long)MTOT * D;
    const long long ATTN = (long long)BATCH * NH * SEQ * WN;
    if ((long long)out_size >= OUTN + ATTN) attn_out = out + OUTN;

    static bool attr_set = false;
    if (!attr_set) {
        cudaFuncSetAttribute(qkv_gemm_mma, cudaFuncAttributeMaxDynamicSharedMemorySize, GEMM_SMEM);
        attr_set = true;
    }

    convert_x<<<(MTOT * D / 4) / 256, 256>>>(X);
    convert_w<<<(3 * D * D) / 256, 256>>>(Wq, Wk, Wv);

    dim3 grid(MTOT / BM, D / BN, 3);
    qkv_gemm_mma<<<grid, 256, GEMM_SMEM>>>(bq, bk, bv);

    const int warps = BATCH * NH * SEQ;
    const int blocks = (warps * 32 + 255) / 256;
    attn_kernel<<<blocks, 256>>>(Er, layer, out, attn_out);
}